// round 8
// baseline (speedup 1.0000x reference)
#include <cuda_runtime.h>
#include <cstddef>

#define NEGF (-10000.0f)
constexpr int S_LEN = 1024;
constexpr int NLAB  = 49;
constexpr int L     = 51;   // start = 49, end = 50

__device__ __forceinline__ unsigned long long pk2(float a, float b) {
    unsigned long long r;
    asm("mov.b64 %0, {%1, %2};" : "=l"(r) : "f"(a), "f"(b));
    return r;
}
__device__ __forceinline__ void upk2(unsigned long long v, float& a, float& b) {
    asm("mov.b64 {%0, %1}, %2;" : "=f"(a), "=f"(b) : "l"(v));
}

#define FMA2(ACC, Q, E) \
    asm("fma.rn.f32x2 %0, %1, %2, %0;" : "+l"(ACC) : "l"(Q), "l"(E))
#define ADD2(DST, A, Bq) \
    asm("add.rn.f32x2 %0, %1, %2;" : "=l"(DST) : "l"(A), "l"(Bq))

__global__ __launch_bounds__(32) void crf_fwd_kernel(
    const float* __restrict__ logits,   // [B, S, NL]
    const float* __restrict__ trans,    // [L, L]
    const int*   __restrict__ labels,   // [B, S]
    const int*   __restrict__ lens,     // [B]
    float*       __restrict__ out)      // [B]
{
    __shared__ __align__(16) float qsh[2][56];   // slots 49..55 stay 0
    __shared__ float norm_sh;

    const int b    = blockIdx.x;
    const int lane = threadIdx.x;
    const int len  = lens[b];

    // lo row = state 'lane'; hi row = state lane+32 (lanes 0..16), lane 17 hi = end(50)
    const bool hasHiQ   = lane < 17;
    const int  hiRow    = hasHiQ ? (lane + 32) : (lane == 17 ? 50 : 0);
    const bool hasHiRow = lane <= 17;

    // ---- exp(T[row, k]) for k = 0..49, packed 25 f32x2 per row ----
    unsigned long long eLo[25], eHi[25];
    {
        const float* rlo = trans + lane * L;
        const float* rhi = trans + hiRow * L;
        #pragma unroll
        for (int p = 0; p < 25; p++) {
            eLo[p] = pk2(__expf(rlo[2 * p]), __expf(rlo[2 * p + 1]));
            float d = 0.0f, e = 0.0f;
            if (hasHiRow) { d = __expf(rhi[2 * p]); e = __expf(rhi[2 * p + 1]); }
            eHi[p] = pk2(d, e);
        }
    }

    // ---- init: q1[j] = exp(lg0[j] + T[j, start=49]); everything else 0 ----
    for (int i = lane; i < 56; i += 32) { qsh[0][i] = 0.0f; qsh[1][i] = 0.0f; }
    __syncwarp();
    const float* lp = logits + (size_t)b * S_LEN * NLAB;
    qsh[1][lane] = __expf(__ldg(lp + lane) + __ldg(trans + lane * L + 49));
    if (hasHiQ)
        qsh[1][lane + 32] =
            __expf(__ldg(lp + lane + 32) + __ldg(trans + (lane + 32) * L + 49));

    // ---- prefetch ring for t = 1..8 ----
    const int ciHi = hasHiQ ? (lane + 32) : 0;
    float rl[8], rh[8];
    #pragma unroll
    for (int j = 0; j < 8; j++) {
        rl[j] = __ldg(lp + (size_t)(1 + j) * NLAB + lane);
        rh[j] = __ldg(lp + (size_t)(1 + j) * NLAB + ciHi);
    }

    int Eacc = 0;   // lane-uniform: sum of applied scale exponents (log2)
    __syncwarp();

    for (int tb = 1; tb < len; tb += 8) {
        float vl[8], vh[8];
        #pragma unroll
        for (int j = 0; j < 8; j++) {
            vl[j] = __expf(rl[j]);
            vh[j] = hasHiQ ? __expf(rh[j]) : 0.0f;
        }

        #pragma unroll
        for (int j = 0; j < 8; j++) {
            const int t = tb + j;
            if (t >= len) break;
            const int par = t & 1;

            const ulonglong2* qp = reinterpret_cast<const ulonglong2*>(qsh[par]);

            // branch-free prefetch of row t+8 (clamped; extra data unused)
            {
                int tp = t + 8 < S_LEN - 1 ? t + 8 : S_LEN - 1;
                rl[j] = __ldg(lp + (size_t)tp * NLAB + lane);
                rh[j] = __ldg(lp + (size_t)tp * NLAB + ciHi);
            }

            unsigned long long c0 = 0ull, c1 = 0ull, d0 = 0ull, d1 = 0ull;
            ulonglong2 qa = qp[0];

            // lag-0 pow2 rescale from q_t[0]'s exponent bits (pure ALU, uniform)
            unsigned int q0bits = (unsigned int)qa.x;
            int be = (int)(q0bits >> 23);           // q0 > 0
            Eacc += be - 127;
            float sc  = __int_as_float((254 - be) << 23);
            float ulo = vl[j] * sc;
            float uhi = vh[j] * sc;

            FMA2(c0, qa.x, eLo[0]);  FMA2(d0, qa.x, eHi[0]);
            FMA2(c1, qa.y, eLo[1]);  FMA2(d1, qa.y, eHi[1]);
            #pragma unroll
            for (int m = 0; m < 6; m++) {
                ulonglong2 qb = qp[2 * m + 1];
                FMA2(c0, qb.x, eLo[4 * m + 2]);  FMA2(d0, qb.x, eHi[4 * m + 2]);
                FMA2(c1, qb.y, eLo[4 * m + 3]);  FMA2(d1, qb.y, eHi[4 * m + 3]);
                ulonglong2 qc = qp[2 * m + 2];
                FMA2(c0, qc.x, eLo[4 * m + 4]);  FMA2(d0, qc.x, eHi[4 * m + 4]);
                if (m < 5) {
                    FMA2(c1, qc.y, eLo[4 * m + 5]);  FMA2(d1, qc.y, eHi[4 * m + 5]);
                }
            }

            unsigned long long slo, shiv;
            ADD2(slo,  c0, c1);
            ADD2(shiv, d0, d1);
            float a0, a1, b0, b1;
            upk2(slo,  a0, a1);
            upk2(shiv, b0, b1);
            float Slo = a0 + a1;
            float Shi = b0 + b1;

            qsh[par ^ 1][lane] = Slo * ulo;
            if (hasHiQ) qsh[par ^ 1][lane + 32] = Shi * uhi;
            __syncwarp();
        }
    }

    // ---- norm = log(Send) + Eacc*ln2 ; Send = lane17's hi-row dot over q_len ----
    {
        const ulonglong2* qp = reinterpret_cast<const ulonglong2*>(qsh[len & 1]);
        unsigned long long d0 = 0ull, d1 = 0ull;
        #pragma unroll
        for (int m = 0; m < 12; m++) {
            ulonglong2 qa = qp[m];
            FMA2(d0, qa.x, eHi[2 * m]);
            FMA2(d1, qa.y, eHi[2 * m + 1]);
        }
        { ulonglong2 qa = qp[12]; FMA2(d0, qa.x, eHi[24]); }
        unsigned long long s; ADD2(s, d0, d1);
        float z0, z1; upk2(s, z0, z1);
        float Send = z0 + z1;
        if (lane == 17)
            norm_sh = (float)((double)__logf(Send) +
                              (double)Eacc * 0.6931471805599453);
    }
    __syncwarp();

    // ---- gold = unary + binary (parallel gather) ----
    const int* labp = labels + (size_t)b * S_LEN;
    float acc = 0.0f;
    #pragma unroll 4
    for (int t = lane; t < len; t += 32) {
        int lab = labp[t];
        acc += __ldg(lp + (size_t)t * NLAB + lab);
        int prev = t ? labp[t - 1] : (L - 2);
        acc += __ldg(trans + lab * L + prev);
    }
    if (lane == 0) acc += __ldg(trans + (L - 1) * L + labp[len - 1]);
    #pragma unroll
    for (int o = 16; o; o >>= 1) acc += __shfl_down_sync(0xffffffffu, acc, o);

    if (lane == 0) out[b] = acc - norm_sh;
}

extern "C" void kernel_launch(void* const* d_in, const int* in_sizes, int n_in,
                              void* d_out, int out_size)
{
    const float* logits = (const float*)d_in[0];
    const float* trans  = (const float*)d_in[1];
    const int*   labels = (const int*)d_in[2];
    const int*   lens   = (const int*)d_in[3];
    const int B = in_sizes[3];
    crf_fwd_kernel<<<B, 32>>>(logits, trans, labels, lens, (float*)d_out);
}

// round 9
// speedup vs baseline: 1.2801x; 1.2801x over previous
#include <cuda_runtime.h>
#include <cstddef>

#define NEGF (-10000.0f)
constexpr int S_LEN = 1024;
constexpr int NLAB  = 49;
constexpr int L     = 51;   // start = 49, end = 50

__device__ __forceinline__ unsigned long long pk2(float a, float b) {
    unsigned long long r;
    asm("mov.b64 %0, {%1, %2};" : "=l"(r) : "f"(a), "f"(b));
    return r;
}
__device__ __forceinline__ void upk2(unsigned long long v, float& a, float& b) {
    asm("mov.b64 {%0, %1}, %2;" : "=f"(a), "=f"(b) : "l"(v));
}

// 25-pack dot over k = 0..49 (q[49] == 0 kills the pad half of pack 24).
// Loads q from shared INSIDE the macro (ptxas schedules them); 2 chains per dot,
// exactly the R4 structure that measured fastest.
#define DOTQ(QP, EARR, OUT)                                                       \
    do {                                                                          \
        unsigned long long c0 = 0ull, c1 = 0ull;                                  \
        _Pragma("unroll")                                                         \
        for (int m = 0; m < 12; m++) {                                            \
            ulonglong2 qv = (QP)[m];                                              \
            asm("fma.rn.f32x2 %0, %1, %2, %0;" : "+l"(c0) : "l"(qv.x), "l"(EARR[2*m]));   \
            asm("fma.rn.f32x2 %0, %1, %2, %0;" : "+l"(c1) : "l"(qv.y), "l"(EARR[2*m+1])); \
        }                                                                         \
        {                                                                         \
            ulonglong2 qv = (QP)[12];                                             \
            asm("fma.rn.f32x2 %0, %1, %2, %0;" : "+l"(c0) : "l"(qv.x), "l"(EARR[24]));    \
        }                                                                         \
        unsigned long long sall;                                                  \
        asm("add.rn.f32x2 %0, %1, %2;" : "=l"(sall) : "l"(c0), "l"(c1));          \
        float z0, z1;                                                             \
        upk2(sall, z0, z1);                                                       \
        OUT = z0 + z1;                                                            \
    } while (0)

__global__ __launch_bounds__(32) void crf_fwd_kernel(
    const float* __restrict__ logits,   // [B, S, NL]
    const float* __restrict__ trans,    // [L, L]
    const int*   __restrict__ labels,   // [B, S]
    const int*   __restrict__ lens,     // [B]
    float*       __restrict__ out)      // [B]
{
    __shared__ __align__(16) float qsh[2][56];   // slots 49..55 stay 0
    __shared__ float norm_sh;

    const int b    = blockIdx.x;
    const int lane = threadIdx.x;
    const int len  = lens[b];

    // lo row = state 'lane'; hi row = state lane+32.
    // q writes: lo always (lane<49 ⊂ all lanes... lanes 49+ don't exist), hi lanes 0..16.
    // lane 18 hi row = 50 (end) is needed only for the final norm dot.
    const bool hasHiQ  = (lane + 32) < NLAB;   // lanes 0..16 write q[32+lane]
    const bool hasHiRw = (lane + 32) < L && lane != 17;  // rows 32..48 and 50
    const int  hiRow   = (lane + 32) < L ? (lane + 32) : 32;

    // ---- exp(T[row, k]) for k = 0..49, packed 25 f32x2 per row ----
    unsigned long long eLo[25], eHi[25];
    {
        const float* rlo = trans + lane * L;
        const float* rhi = trans + hiRow * L;
        #pragma unroll
        for (int p = 0; p < 25; p++) {
            eLo[p] = pk2(__expf(rlo[2 * p]), __expf(rlo[2 * p + 1]));
            float d = 0.0f, e = 0.0f;
            if (hasHiRw) { d = __expf(rhi[2 * p]); e = __expf(rhi[2 * p + 1]); }
            eHi[p] = pk2(d, e);
        }
    }

    // ---- init: q1[j] = exp(lg0[j] + T[j, start=49]); all else 0 ----
    for (int i = lane; i < 56; i += 32) { qsh[0][i] = 0.0f; qsh[1][i] = 0.0f; }
    __syncwarp();
    const float* lp = logits + (size_t)b * S_LEN * NLAB;
    qsh[1][lane] = __expf(__ldg(lp + lane) + __ldg(trans + lane * L + 49));
    if (hasHiQ)
        qsh[1][lane + 32] =
            __expf(__ldg(lp + lane + 32) + __ldg(trans + (lane + 32) * L + 49));

    // ---- prefetch ring for t = 1..8 ----
    const int ciHi = hasHiQ ? (lane + 32) : 0;
    float rl[8], rh[8];
    #pragma unroll
    for (int i = 0; i < 8; i++) {
        rl[i] = __ldg(lp + (size_t)(1 + i) * NLAB + lane);
        rh[i] = hasHiQ ? __ldg(lp + (size_t)(1 + i) * NLAB + ciHi) : NEGF;
    }

    // pipeline: v for step t computed during step t-1
    float vlo = __expf(rl[0]);
    float vhi = hasHiQ ? __expf(rh[0]) : 0.0f;
    int Eacc = 0;   // lane-uniform sum of applied scale exponents (log2)
    __syncwarp();

    for (int tb = 1; tb < len; tb += 8) {
        #pragma unroll
        for (int i = 0; i < 8; i++) {
            const int t = tb + i;
            if (t >= len) break;
            const int par = t & 1;

            const ulonglong2* qp = reinterpret_cast<const ulonglong2*>(qsh[par]);

            // lag-0 pow2 rescale from q_t[0] (scalar broadcast LDS, pure ALU)
            float q0 = qsh[par][0];
            int be = __float_as_int(q0) >> 23;       // q0 > 0
            Eacc += be - 127;
            float sc  = __int_as_float((254 - be) << 23);
            float ulo = vlo * sc;
            float uhi = vhi * sc;

            // off-path: v for step t+1, prefetch row t+8
            const int ni = (i + 1) & 7;
            float vloN = __expf(rl[ni]);
            float vhiN = hasHiQ ? __expf(rh[ni]) : 0.0f;
            if (lane < NLAB && t + 8 < len) {
                rl[i] = __ldg(lp + (size_t)(t + 8) * NLAB + lane);
                if (hasHiQ) rh[i] = __ldg(lp + (size_t)(t + 8) * NLAB + ciHi);
            }

            float Slo, Shi;
            DOTQ(qp, eLo, Slo);
            DOTQ(qp, eHi, Shi);

            qsh[par ^ 1][lane] = Slo * ulo;
            if (hasHiQ) qsh[par ^ 1][lane + 32] = Shi * uhi;
            __syncwarp();

            vlo = vloN; vhi = vhiN;
        }
    }

    // ---- norm = log(Send) + Eacc*ln2 ; Send = lane 18's hi row (end=50) ----
    {
        const ulonglong2* qp = reinterpret_cast<const ulonglong2*>(qsh[len & 1]);
        float Send;
        DOTQ(qp, eHi, Send);
        if (lane == 18)
            norm_sh = (float)((double)__logf(Send) +
                              (double)Eacc * 0.6931471805599453);
    }
    __syncwarp();

    // ---- gold = unary + binary (parallel gather) ----
    const int* labp = labels + (size_t)b * S_LEN;
    float acc = 0.0f;
    #pragma unroll 4
    for (int t = lane; t < len; t += 32) {
        int lab = labp[t];
        acc += __ldg(lp + (size_t)t * NLAB + lab);
        int prev = t ? labp[t - 1] : (L - 2);
        acc += __ldg(trans + lab * L + prev);
    }
    if (lane == 0) acc += __ldg(trans + (L - 1) * L + labp[len - 1]);
    #pragma unroll
    for (int o = 16; o; o >>= 1) acc += __shfl_down_sync(0xffffffffu, acc, o);

    if (lane == 0) out[b] = acc - norm_sh;
}

extern "C" void kernel_launch(void* const* d_in, const int* in_sizes, int n_in,
                              void* d_out, int out_size)
{
    const float* logits = (const float*)d_in[0];
    const float* trans  = (const float*)d_in[1];
    const int*   labels = (const int*)d_in[2];
    const int*   lens   = (const int*)d_in[3];
    const int B = in_sizes[3];
    crf_fwd_kernel<<<B, 32>>>(logits, trans, labels, lens, (float*)d_out);
}

// round 10
// speedup vs baseline: 1.7600x; 1.3748x over previous
#include <cuda_runtime.h>
#include <cstddef>

#define NEGF (-10000.0f)
constexpr int S_LEN = 1024;
constexpr int NLAB  = 49;
constexpr int L     = 51;   // start = 49, end = 50

__device__ __forceinline__ unsigned long long pk2(float a, float b) {
    unsigned long long r;
    asm("mov.b64 %0, {%1, %2};" : "=l"(r) : "f"(a), "f"(b));
    return r;
}
__device__ __forceinline__ void upk2(unsigned long long v, float& a, float& b) {
    asm("mov.b64 {%0, %1}, %2;" : "=f"(a), "=f"(b) : "l"(v));
}

// 25-pack dot over index 0..49 of a 56-float shared vector (slots >=49 are 0 or
// paired with zero coefficients). Loads stay inside so ptxas schedules them.
#define DOTQ(QP, EARR, OUT)                                                       \
    do {                                                                          \
        unsigned long long c0 = 0ull, c1 = 0ull;                                  \
        _Pragma("unroll")                                                         \
        for (int mm = 0; mm < 12; mm++) {                                         \
            ulonglong2 qv = (QP)[mm];                                             \
            asm("fma.rn.f32x2 %0, %1, %2, %0;" : "+l"(c0) : "l"(qv.x), "l"(EARR[2*mm]));   \
            asm("fma.rn.f32x2 %0, %1, %2, %0;" : "+l"(c1) : "l"(qv.y), "l"(EARR[2*mm+1])); \
        }                                                                         \
        {                                                                         \
            ulonglong2 qv = (QP)[12];                                             \
            asm("fma.rn.f32x2 %0, %1, %2, %0;" : "+l"(c0) : "l"(qv.x), "l"(EARR[24]));     \
        }                                                                         \
        unsigned long long sall;                                                  \
        asm("add.rn.f32x2 %0, %1, %2;" : "=l"(sall) : "l"(c0), "l"(c1));          \
        float z0, z1;                                                             \
        upk2(sall, z0, z1);                                                       \
        OUT = z0 + z1;                                                            \
    } while (0)

__global__ __launch_bounds__(64) void crf_fwd_kernel(
    const float* __restrict__ logits,   // [B, S, NL]
    const float* __restrict__ trans,    // [L, L]
    const int*   __restrict__ labels,   // [B, S]
    const int*   __restrict__ lens,     // [B]
    float*       __restrict__ out)      // [B]
{
    __shared__ __align__(16) float ash[2][56];   // forward alpha (slots 49..55 = 0)
    __shared__ __align__(16) float wsh[2][56];   // backward w = v*beta (padded)
    __shared__ __align__(16) float bsh[56];      // beta_m output
    __shared__ float norm_sh;
    __shared__ int   eaccB_sh;
    __shared__ float red[64];

    const int b    = blockIdx.x;
    const int tid  = threadIdx.x;
    const int wid  = tid >> 5;
    const int lane = tid & 31;
    const int len  = lens[b];
    const int m    = (len + 1) >> 1;    // forward: m steps (t=0 folded); backward: len-m

    const float* lp = logits + (size_t)b * S_LEN * NLAB;
    const bool hasHi = lane < 17;       // second state/column = lane+32 (32..48)
    const int  hi    = lane + 32;

    int Eacc = 0;                       // per-warp scale-exponent accumulator

    if (wid == 0) {
        // ================= FORWARD (rows of E) =================
        unsigned long long eLo[25], eHi[25];
        {
            const float* rlo = trans + lane * L;
            const float* rhi = trans + (hasHi ? hi : 0) * L;
            #pragma unroll
            for (int p = 0; p < 25; p++) {
                eLo[p] = pk2(__expf(rlo[2 * p]), __expf(rlo[2 * p + 1]));
                float d = 0.0f, e = 0.0f;
                if (hasHi) { d = __expf(rhi[2 * p]); e = __expf(rhi[2 * p + 1]); }
                eHi[p] = pk2(d, e);
            }
        }
        for (int i = lane; i < 56; i += 32) { ash[0][i] = 0.0f; ash[1][i] = 0.0f; }
        __syncwarp();
        // alpha_1[j] = exp(lg0[j] + T[j, start=49])
        ash[1][lane] = __expf(__ldg(lp + lane) + __ldg(trans + lane * L + 49));
        if (hasHi)
            ash[1][hi] = __expf(__ldg(lp + hi) + __ldg(trans + hi * L + 49));

        float rl[8], rh[8];
        #pragma unroll
        for (int i = 0; i < 8; i++) {
            rl[i] = __ldg(lp + (size_t)(1 + i) * NLAB + lane);
            rh[i] = hasHi ? __ldg(lp + (size_t)(1 + i) * NLAB + hi) : NEGF;
        }
        float vlo = __expf(rl[0]);
        float vhi = hasHi ? __expf(rh[0]) : 0.0f;
        __syncwarp();

        for (int tb = 1; tb < m; tb += 8) {
            #pragma unroll
            for (int i = 0; i < 8; i++) {
                const int t = tb + i;
                if (t >= m) break;
                const int par = t & 1;
                const ulonglong2* qp = reinterpret_cast<const ulonglong2*>(ash[par]);

                float q0 = ash[par][0];
                int be = __float_as_int(q0) >> 23;       // q0 > 0
                Eacc += be - 127;
                float sc  = __int_as_float((254 - be) << 23);
                float ulo = vlo * sc;
                float uhi = vhi * sc;

                const int ni = (i + 1) & 7;
                float vloN = __expf(rl[ni]);
                float vhiN = hasHi ? __expf(rh[ni]) : 0.0f;
                if (t + 8 < m) {
                    rl[i] = __ldg(lp + (size_t)(t + 8) * NLAB + lane);
                    if (hasHi) rh[i] = __ldg(lp + (size_t)(t + 8) * NLAB + hi);
                }

                float Slo, Shi;
                DOTQ(qp, eLo, Slo);
                DOTQ(qp, eHi, Shi);

                ash[par ^ 1][lane] = Slo * ulo;
                if (hasHi) ash[par ^ 1][hi] = Shi * uhi;
                __syncwarp();
                vlo = vloN; vhi = vhiN;
            }
        }
    } else {
        // ================= BACKWARD (columns of E) =================
        unsigned long long eLo[25], eHi[25];
        #pragma unroll
        for (int p = 0; p < 25; p++) {
            eLo[p] = pk2(__expf(__ldg(trans + (2 * p) * L + lane)),
                         __expf(__ldg(trans + (2 * p + 1) * L + lane)));
            float d = 0.0f, e = 0.0f;
            if (hasHi) {
                d = __expf(__ldg(trans + (2 * p) * L + hi));
                e = __expf(__ldg(trans + (2 * p + 1) * L + hi));
            }
            eHi[p] = pk2(d, e);
        }
        // beta_len = r : r[j] = exp(T[end=50, j])
        float blo = __expf(__ldg(trans + 50 * L + lane));
        float bhi = hasHi ? __expf(__ldg(trans + 50 * L + hi)) : 0.0f;

        for (int i = lane; i < 56; i += 32) { wsh[0][i] = 0.0f; wsh[1][i] = 0.0f; bsh[i] = 0.0f; }
        __syncwarp();
        if (lane == 0) { wsh[0][0] = 1.0f; wsh[1][0] = 1.0f; }  // first-step sc = 1
        __syncwarp();

        float rl[8], rh[8];
        #pragma unroll
        for (int i = 0; i < 8; i++) {
            int tr = len - 1 - i >= 0 ? len - 1 - i : 0;
            rl[i] = __ldg(lp + (size_t)tr * NLAB + lane);
            rh[i] = hasHi ? __ldg(lp + (size_t)tr * NLAB + hi) : NEGF;
        }
        float vlo = __expf(rl[0]);
        float vhi = hasHi ? __expf(rh[0]) : 0.0f;
        __syncwarp();

        for (int tb = len - 1; tb >= m; tb -= 8) {
            #pragma unroll
            for (int i = 0; i < 8; i++) {
                const int t = tb - i;
                if (t < m) break;
                const int par = t & 1;

                float w0 = wsh[par ^ 1][0];              // stored by previous step
                int be = __float_as_int(w0) >> 23;       // w0 > 0
                Eacc += be - 127;
                float sc = __int_as_float((254 - be) << 23);

                wsh[par][lane] = vlo * blo * sc;
                if (hasHi) wsh[par][hi] = vhi * bhi * sc;
                __syncwarp();

                const int ni = (i + 1) & 7;
                float vloN = __expf(rl[ni]);
                float vhiN = hasHi ? __expf(rh[ni]) : 0.0f;
                if (t - 8 >= m) {
                    rl[i] = __ldg(lp + (size_t)(t - 8) * NLAB + lane);
                    if (hasHi) rh[i] = __ldg(lp + (size_t)(t - 8) * NLAB + hi);
                }

                const ulonglong2* qp = reinterpret_cast<const ulonglong2*>(wsh[par]);
                float Sl, Sh;
                DOTQ(qp, eLo, Sl);
                DOTQ(qp, eHi, Sh);
                blo = Sl;
                bhi = hasHi ? Sh : 0.0f;
                vlo = vloN; vhi = vhiN;
            }
        }
        bsh[lane] = blo;
        if (hasHi) bsh[hi] = bhi;
        if (lane == 0) eaccB_sh = Eacc;
    }
    __syncthreads();

    // ---- Z = alpha_m . beta_m ; norm = log Z + (EF+EB) ln2  (warp 0) ----
    if (wid == 0) {
        const int fpar = m & 1;
        float z = ash[fpar][lane] * bsh[lane];
        if (hasHi) z += ash[fpar][hi] * bsh[hi];
        #pragma unroll
        for (int o = 16; o; o >>= 1) z += __shfl_down_sync(0xffffffffu, z, o);
        if (lane == 0)
            norm_sh = (float)((double)__logf(z) +
                              (double)(Eacc + eaccB_sh) * 0.6931471805599453);
    }

    // ---- gold = unary + binary (64-thread gather) ----
    const int* labp = labels + (size_t)b * S_LEN;
    float acc = 0.0f;
    #pragma unroll 4
    for (int t = tid; t < len; t += 64) {
        int lab = labp[t];
        acc += __ldg(lp + (size_t)t * NLAB + lab);
        int prev = t ? labp[t - 1] : (L - 2);
        acc += __ldg(trans + lab * L + prev);
    }
    if (tid == 0) acc += __ldg(trans + 50 * L + labp[len - 1]);
    red[tid] = acc;
    __syncthreads();

    if (tid < 32) {
        float v = red[tid] + red[tid + 32];
        #pragma unroll
        for (int o = 16; o; o >>= 1) v += __shfl_down_sync(0xffffffffu, v, o);
        if (tid == 0) out[b] = v - norm_sh;
    }
}

extern "C" void kernel_launch(void* const* d_in, const int* in_sizes, int n_in,
                              void* d_out, int out_size)
{
    const float* logits = (const float*)d_in[0];
    const float* trans  = (const float*)d_in[1];
    const int*   labels = (const int*)d_in[2];
    const int*   lens   = (const int*)d_in[3];
    const int B = in_sizes[3];
    crf_fwd_kernel<<<B, 64>>>(logits, trans, labels, lens, (float*)d_out);
}